// round 5
// baseline (speedup 1.0000x reference)
#include <cuda_runtime.h>
#include <cuda_bf16.h>

#define BINS 10

// Global scratch (allocation-free requirement): per-bin count and loss sums.
static __device__ float g_cnt[BINS];
static __device__ float g_sum[BINS];

__global__ void ghm_init() {
    if (threadIdx.x < BINS) {
        g_cnt[threadIdx.x] = 0.0f;
        g_sum[threadIdx.x] = 0.0f;
    }
}

// One warp per row. 256 threads = 8 rows per block.
__global__ __launch_bounds__(256) void ghm_rows(
    const float* __restrict__ pred,
    const int* __restrict__ target,   // JAX int64 is downgraded to int32 (x64 disabled)
    int B, int C)
{
    __shared__ float s_cnt[BINS];
    __shared__ float s_sum[BINS];
    if (threadIdx.x < BINS) { s_cnt[threadIdx.x] = 0.0f; s_sum[threadIdx.x] = 0.0f; }
    __syncthreads();

    const int warp = threadIdx.x >> 5;
    const int lane = threadIdx.x & 31;
    const int row  = blockIdx.x * (blockDim.x >> 5) + warp;

    if (row < B) {
        const size_t base = (size_t)row * (size_t)C;
        const float4* __restrict__ p4 = (const float4*)(pred + base);
        const int n4 = C >> 2;           // 250 for C=1000 (row stride 4000B is 16B-aligned)

        float s = 0.0f;
        #pragma unroll 4
        for (int i = lane; i < n4; i += 32) {
            float4 v = p4[i];
            s += __expf(v.x) + __expf(v.y) + __expf(v.z) + __expf(v.w);
        }
        // tail for C not divisible by 4 (not hit for C=1000)
        for (int j = (n4 << 2) + lane; j < C; j += 32) s += __expf(pred[base + j]);

        // warp reduction
        #pragma unroll
        for (int o = 16; o; o >>= 1) s += __shfl_xor_sync(0xffffffffu, s, o);

        if (lane == 0) {
            int t = target[row];
            t = t < 0 ? 0 : (t >= C ? C - 1 : t);   // crash-guard; rel_err catches misuse
            const float tv = pred[base + (size_t)t];
            const float g = 1.0f - __expf(tv) / s;
            int b = (int)floorf(g * 10.0f);
            b = b < 0 ? 0 : (b > BINS - 1 ? BINS - 1 : b);
            const float loss = -tv + __logf(s + 1e-8f);
            atomicAdd(&s_cnt[b], 1.0f);
            atomicAdd(&s_sum[b], loss);
        }
    }

    __syncthreads();
    if (threadIdx.x < BINS) {
        float c = s_cnt[threadIdx.x];
        float l = s_sum[threadIdx.x];
        if (c != 0.0f) {
            atomicAdd(&g_cnt[threadIdx.x], c);
            atomicAdd(&g_sum[threadIdx.x], l);
        }
    }
}

__global__ void ghm_final(float* __restrict__ out) {
    if (threadIdx.x == 0) {
        float n_nonempty = 0.0f;
        float tot = 0.0f;
        #pragma unroll
        for (int b = 0; b < BINS; ++b) {
            float c = g_cnt[b];
            if (c > 0.0f) {
                n_nonempty += 1.0f;
                tot += g_sum[b] / c;
            }
        }
        out[0] = tot / fmaxf(n_nonempty, 1.0f);
    }
}

extern "C" void kernel_launch(void* const* d_in, const int* in_sizes, int n_in,
                              void* d_out, int out_size) {
    const float* pred   = (const float*)d_in[0];
    const int*   target = (const int*)d_in[1];
    float*       out    = (float*)d_out;

    const int B = in_sizes[1];            // 65536 rows
    const int C = in_sizes[0] / B;        // 1000 classes

    ghm_init<<<1, 32>>>();

    const int warps_per_block = 8;        // 256 threads
    const int grid = (B + warps_per_block - 1) / warps_per_block;
    ghm_rows<<<grid, 256>>>(pred, target, B, C);

    ghm_final<<<1, 32>>>(out);
}